// round 8
// baseline (speedup 1.0000x reference)
#include <cuda_runtime.h>
#include <cuda_bf16.h>
#include <cstdint>

// ---------------------------------------------------------------------------
// SSMDecoder: ys = 2*Re( scan(exp(L*dt), x@B_bar^T) @ C^T ) + D*x
// Bsz=8, L=4096, H=512, P=256 (complex state as re/im planes, N2=512).
// GEMMs via mma.sync m16n8k16 bf16 with 3x hi/lo split; all fp32->bf16
// conversions hoisted out of the GEMM inner loops into one-shot passes.
// ---------------------------------------------------------------------------

#define BSZ 8
#define LEN 4096
#define HH  512
#define PP  256
#define N2  512
#define MT  (BSZ*LEN)           // 32768
#define CHUNK 64
#define NCHUNK (LEN/CHUNK)      // 64
#define KT  512
#define NT  512

typedef __nv_bfloat16 bf16;

// ------------------------------- scratch -----------------------------------
__device__ float g_Bu[(size_t)MT * N2];                    // 64 MB
__device__ __align__(16) bf16 g_xh[(size_t)MT * N2];       // 32 MB
__device__ __align__(16) bf16 g_xl[(size_t)MT * N2];       // 32 MB
__device__ __align__(16) bf16 g_Xh[(size_t)MT * N2];       // 32 MB (xs hi)
__device__ __align__(16) bf16 g_Xl[(size_t)MT * N2];       // 32 MB (xs lo)
__device__ __align__(16) bf16 g_G1h[N2 * HH];
__device__ __align__(16) bf16 g_G1l[N2 * HH];
__device__ __align__(16) bf16 g_G2h[HH * N2];
__device__ __align__(16) bf16 g_G2l[HH * N2];
__device__ float g_lam[2 * PP];
__device__ float g_f[2 * PP];
__device__ float g_pow[(CHUNK + 1) * N2];
__device__ float g_cs[BSZ * NCHUNK * N2];
__device__ float g_carry[BSZ * NCHUNK * N2];

// ------------------------------ helpers ------------------------------------
__device__ __forceinline__ uint32_t smem_u32(const void* p) {
    uint32_t a;
    asm("{ .reg .u64 t; cvta.to.shared.u64 t, %1; cvt.u32.u64 %0, t; }"
        : "=r"(a) : "l"(p));
    return a;
}
__device__ __forceinline__ void ldsm4(uint32_t* r, uint32_t addr) {
    asm volatile("ldmatrix.sync.aligned.m8n8.x4.shared.b16 {%0,%1,%2,%3}, [%4];"
                 : "=r"(r[0]), "=r"(r[1]), "=r"(r[2]), "=r"(r[3]) : "r"(addr));
}
__device__ __forceinline__ void mma_bf16(float* c, const uint32_t* a, const uint32_t* b) {
    asm volatile(
        "mma.sync.aligned.m16n8k16.row.col.f32.bf16.bf16.f32 "
        "{%0,%1,%2,%3}, {%4,%5,%6,%7}, {%8,%9}, {%0,%1,%2,%3};"
        : "+f"(c[0]), "+f"(c[1]), "+f"(c[2]), "+f"(c[3])
        : "r"(a[0]), "r"(a[1]), "r"(a[2]), "r"(a[3]), "r"(b[0]), "r"(b[1]));
}
__device__ __forceinline__ uint32_t packbf(float x, float y) {
    __nv_bfloat162 t = __floats2bfloat162_rn(x, y);
    return *reinterpret_cast<uint32_t*>(&t);
}

// ------------------------------- setup -------------------------------------
__global__ void k_setup(const float* __restrict__ lre,
                        const float* __restrict__ lim,
                        const float* __restrict__ lstep) {
    int p = threadIdx.x;
    if (p >= PP) return;
    float st = expf(lstep[p]);
    float ar = lre[p], ai = lim[p];
    float e  = expf(ar * st);
    float th = ai * st;
    float lr = e * cosf(th), li = e * sinf(th);
    g_lam[p] = lr; g_lam[PP + p] = li;
    float nr = lr - 1.0f, ni = li;
    float den = ar * ar + ai * ai;
    g_f[p]      = (nr * ar + ni * ai) / den;
    g_f[PP + p] = (ni * ar - nr * ai) / den;
    float pr = 1.0f, pi = 0.0f;
    for (int k = 0; k <= CHUNK; k++) {
        g_pow[k * N2 + p]      = pr;
        g_pow[k * N2 + PP + p] = pi;
        float t = pr * lr - pi * li;
        pi = pr * li + pi * lr;
        pr = t;
    }
}

__global__ void k_fill(const float* __restrict__ Bm, const float* __restrict__ Cm) {
    int tid = blockIdx.x * blockDim.x + threadIdx.x;
    if (tid >= N2 * HH) return;
    {   // G1[n][h]
        int n = tid / HH, h = tid - n * HH;
        int p = n & (PP - 1);
        float fr = g_f[p], fi = g_f[PP + p];
        float b0 = Bm[(p * HH + h) * 2], b1 = Bm[(p * HH + h) * 2 + 1];
        float v = (n < PP) ? (fr * b0 - fi * b1) : (fr * b1 + fi * b0);
        bf16 hi = __float2bfloat16(v);
        g_G1h[tid] = hi;
        g_G1l[tid] = __float2bfloat16(v - __bfloat162float(hi));
    }
    {   // G2[h][n]
        int h = tid / N2, n = tid - h * N2;
        float v;
        if (n < PP) v =  2.0f * Cm[(h * PP + n) * 2];
        else        v = -2.0f * Cm[(h * PP + (n - PP)) * 2 + 1];
        bf16 hi = __float2bfloat16(v);
        g_G2h[tid] = hi;
        g_G2l[tid] = __float2bfloat16(v - __bfloat162float(hi));
    }
}

// x -> bf16 hi/lo planes (one shot)
__global__ void k_xconv(const float* __restrict__ x) {
    size_t i4 = (size_t)blockIdx.x * blockDim.x + threadIdx.x;  // float4 index
    float4 v = *(const float4*)(x + i4 * 4);
    float h0 = __bfloat162float(__float2bfloat16(v.x));
    float h1 = __bfloat162float(__float2bfloat16(v.y));
    float h2 = __bfloat162float(__float2bfloat16(v.z));
    float h3 = __bfloat162float(__float2bfloat16(v.w));
    uint2 hp = make_uint2(packbf(h0, h1), packbf(h2, h3));
    uint2 lp = make_uint2(packbf(v.x - h0, v.y - h1), packbf(v.z - h2, v.w - h3));
    *(uint2*)(g_xh + i4 * 4) = hp;
    *(uint2*)(g_xl + i4 * 4) = lp;
}

// --------------------------- mma.sync GEMM ---------------------------------
// CTA 128x128, K-chunk 32, 256 threads = 8 warps (2M x 4N), warp 64x32.
// SMEM per stage: 4 bf16 planes (Ah, Al, Bh, Bl), rows padded to 40 bf16.

#define AROW  40
#define PLANE (128 * AROW * 2)          // 10240 B
#define STAGE (4 * PLANE)               // 40960 B
#define GSMEM (2 * STAGE)               // 81920 B

template <bool EPI>
__device__ __forceinline__ void gemm_mma(const bf16* __restrict__ Ah,
                                         const bf16* __restrict__ Al,
                                         const bf16* __restrict__ Bh,
                                         const bf16* __restrict__ Bl,
                                         float* __restrict__ Cg,
                                         const float* __restrict__ Xg,
                                         const float* __restrict__ Dg) {
    extern __shared__ __align__(16) char smem[];
    const uint32_t sb = smem_u32(smem);
    const int tid = threadIdx.x;
    const int wid = tid >> 5;
    const int l   = tid & 31;
    const int warp_m = wid >> 2;
    const int warp_n = wid & 3;
    const int rowBase = blockIdx.y * 128;
    const int colBase = blockIdx.x * 128;

    const bf16* aH = Ah + (size_t)rowBase * KT;
    const bf16* aL = Al + (size_t)rowBase * KT;
    const bf16* bH = Bh + (size_t)colBase * KT;
    const bf16* bL = Bl + (size_t)colBase * KT;

    const int lr_ = tid >> 2;           // 0..63  (two rows per plane pass)
    const int lc_ = tid & 3;            // 16B column chunk
    // per thread, per plane: rows lr_ and lr_+64  (idx = tid, tid+256)
    const uint32_t stoff0 = (uint32_t)(lr_ * (AROW * 2) + lc_ * 16);
    const uint32_t stoff1 = (uint32_t)((lr_ + 64) * (AROW * 2) + lc_ * 16);
    const size_t ld0 = (size_t)lr_ * KT + lc_ * 8;
    const size_t ld1 = (size_t)(lr_ + 64) * KT + lc_ * 8;

    float acc[4][4][4];
#pragma unroll
    for (int i = 0; i < 4; i++)
#pragma unroll
        for (int j = 0; j < 4; j++)
#pragma unroll
            for (int k = 0; k < 4; k++) acc[i][j][k] = 0.0f;

    uint4 pa[2][2], pl[2][2], pb[2][2], pq[2][2];
    // prefetch kt=0
    pa[0][0] = *(const uint4*)(aH + ld0); pa[0][1] = *(const uint4*)(aH + ld1);
    pl[0][0] = *(const uint4*)(aL + ld0); pl[0][1] = *(const uint4*)(aL + ld1);
    pb[0][0] = *(const uint4*)(bH + ld0); pb[0][1] = *(const uint4*)(bH + ld1);
    pq[0][0] = *(const uint4*)(bL + ld0); pq[0][1] = *(const uint4*)(bL + ld1);

#define STS_STAGE(base, S) do { \
    asm volatile("st.shared.v4.b32 [%0], {%1,%2,%3,%4};" :: "r"((base) + stoff0), \
        "r"(pa[S][0].x), "r"(pa[S][0].y), "r"(pa[S][0].z), "r"(pa[S][0].w) : "memory"); \
    asm volatile("st.shared.v4.b32 [%0], {%1,%2,%3,%4};" :: "r"((base) + stoff1), \
        "r"(pa[S][1].x), "r"(pa[S][1].y), "r"(pa[S][1].z), "r"(pa[S][1].w) : "memory"); \
    asm volatile("st.shared.v4.b32 [%0], {%1,%2,%3,%4};" :: "r"((base) + PLANE + stoff0), \
        "r"(pl[S][0].x), "r"(pl[S][0].y), "r"(pl[S][0].z), "r"(pl[S][0].w) : "memory"); \
    asm volatile("st.shared.v4.b32 [%0], {%1,%2,%3,%4};" :: "r"((base) + PLANE + stoff1), \
        "r"(pl[S][1].x), "r"(pl[S][1].y), "r"(pl[S][1].z), "r"(pl[S][1].w) : "memory"); \
    asm volatile("st.shared.v4.b32 [%0], {%1,%2,%3,%4};" :: "r"((base) + 2*PLANE + stoff0), \
        "r"(pb[S][0].x), "r"(pb[S][0].y), "r"(pb[S][0].z), "r"(pb[S][0].w) : "memory"); \
    asm volatile("st.shared.v4.b32 [%0], {%1,%2,%3,%4};" :: "r"((base) + 2*PLANE + stoff1), \
        "r"(pb[S][1].x), "r"(pb[S][1].y), "r"(pb[S][1].z), "r"(pb[S][1].w) : "memory"); \
    asm volatile("st.shared.v4.b32 [%0], {%1,%2,%3,%4};" :: "r"((base) + 3*PLANE + stoff0), \
        "r"(pq[S][0].x), "r"(pq[S][0].y), "r"(pq[S][0].z), "r"(pq[S][0].w) : "memory"); \
    asm volatile("st.shared.v4.b32 [%0], {%1,%2,%3,%4};" :: "r"((base) + 3*PLANE + stoff1), \
        "r"(pq[S][1].x), "r"(pq[S][1].y), "r"(pq[S][1].z), "r"(pq[S][1].w) : "memory"); \
} while (0)

    STS_STAGE(sb, 0);
    __syncthreads();

    const int a_row = l & 15;
    const int a_k   = (l >> 4) * 8;
    const int b_row = (l & 7) + ((l >> 4) << 3);
    const int b_k   = ((l >> 3) & 1) * 8;

    for (int kt = 0; kt < 16; kt++) {
        const int buf = kt & 1;
        const int pf = buf ^ 1;
        if (kt < 15) {
            const size_t ko = (size_t)(kt + 1) * 32;
            pa[pf][0] = *(const uint4*)(aH + ld0 + ko); pa[pf][1] = *(const uint4*)(aH + ld1 + ko);
            pl[pf][0] = *(const uint4*)(aL + ld0 + ko); pl[pf][1] = *(const uint4*)(aL + ld1 + ko);
            pb[pf][0] = *(const uint4*)(bH + ld0 + ko); pb[pf][1] = *(const uint4*)(bH + ld1 + ko);
            pq[pf][0] = *(const uint4*)(bL + ld0 + ko); pq[pf][1] = *(const uint4*)(bL + ld1 + ko);
        }
        const uint32_t base = sb + buf * STAGE;
#pragma unroll
        for (int kk = 0; kk < 2; kk++) {
            uint32_t aHr[4][4], aLr[4][4], bHr[2][4], bLr[2][4];
            const int acol = kk * 16 + a_k;
            const int bcol = kk * 16 + b_k;
#pragma unroll
            for (int mt = 0; mt < 4; mt++) {
                uint32_t off = (uint32_t)(((warp_m * 64 + mt * 16 + a_row) * AROW + acol) * 2);
                ldsm4(aHr[mt], base + off);
                ldsm4(aLr[mt], base + PLANE + off);
            }
#pragma unroll
            for (int nb = 0; nb < 2; nb++) {
                uint32_t off = (uint32_t)(((warp_n * 32 + nb * 16 + b_row) * AROW + bcol) * 2);
                ldsm4(bHr[nb], base + 2 * PLANE + off);
                ldsm4(bLr[nb], base + 3 * PLANE + off);
            }
#pragma unroll
            for (int mt = 0; mt < 4; mt++)
#pragma unroll
                for (int nt = 0; nt < 4; nt++)
                    mma_bf16(acc[mt][nt], aHr[mt], &bHr[nt >> 1][(nt & 1) * 2]);
#pragma unroll
            for (int mt = 0; mt < 4; mt++)
#pragma unroll
                for (int nt = 0; nt < 4; nt++)
                    mma_bf16(acc[mt][nt], aLr[mt], &bHr[nt >> 1][(nt & 1) * 2]);
#pragma unroll
            for (int mt = 0; mt < 4; mt++)
#pragma unroll
                for (int nt = 0; nt < 4; nt++)
                    mma_bf16(acc[mt][nt], aHr[mt], &bLr[nt >> 1][(nt & 1) * 2]);
        }
        if (kt < 15) STS_STAGE(sb + pf * STAGE, pf);
        __syncthreads();
    }

    // ---- epilogue ----
    const int r0 = l >> 2;
    const int cp = (l & 3) * 2;
#pragma unroll
    for (int mt = 0; mt < 4; mt++) {
#pragma unroll
        for (int nt = 0; nt < 4; nt++) {
            const int row = rowBase + warp_m * 64 + mt * 16 + r0;
            const int col = colBase + warp_n * 32 + nt * 8 + cp;
            float2 v0 = make_float2(acc[mt][nt][0], acc[mt][nt][1]);
            float2 v1 = make_float2(acc[mt][nt][2], acc[mt][nt][3]);
            size_t o0 = (size_t)row * NT + col;
            size_t o1 = (size_t)(row + 8) * NT + col;
            if (EPI) {
                float2 d  = *(const float2*)(Dg + col);
                float2 x0 = *(const float2*)(Xg + o0);
                float2 x1 = *(const float2*)(Xg + o1);
                v0.x += d.x * x0.x; v0.y += d.y * x0.y;
                v1.x += d.x * x1.x; v1.y += d.y * x1.y;
            }
            *(float2*)(Cg + o0) = v0;
            *(float2*)(Cg + o1) = v1;
        }
    }
#undef STS_STAGE
}

__global__ __launch_bounds__(256, 1) void k_gemm1() {
    gemm_mma<false>(g_xh, g_xl, g_G1h, g_G1l, g_Bu, nullptr, nullptr);
}
__global__ __launch_bounds__(256, 1) void k_gemm2(const float* __restrict__ x,
                                                  const float* __restrict__ D,
                                                  float* __restrict__ out) {
    gemm_mma<true>(g_Xh, g_Xl, g_G2h, g_G2l, out, x, D);
}

// ------------------------------- scan --------------------------------------
__global__ void k_scan_local() {
    const int b = blockIdx.x >> 6;
    const int c = blockIdx.x & 63;
    const int p = threadIdx.x;
    const float lr = g_lam[p], li = g_lam[PP + p];
    float sr = 0.0f, si = 0.0f;
    size_t base = (size_t)(b * LEN + c * CHUNK) * N2;
#pragma unroll 4
    for (int j = 0; j < CHUNK; j++) {
        size_t o = base + (size_t)j * N2;
        float ur = g_Bu[o + p], ui = g_Bu[o + PP + p];
        float nr = fmaf(lr, sr, fmaf(-li, si, ur));
        float ni = fmaf(lr, si, fmaf(li, sr, ui));
        g_Bu[o + p] = nr;
        g_Bu[o + PP + p] = ni;
        sr = nr; si = ni;
    }
    int co = (b * NCHUNK + c) * N2;
    g_cs[co + p] = sr;
    g_cs[co + PP + p] = si;
}

__global__ void k_chunkscan() {
    const int b = blockIdx.x;
    const int p = threadIdx.x;
    const float tr = g_pow[CHUNK * N2 + p], ti = g_pow[CHUNK * N2 + PP + p];
    float sr = 0.0f, si = 0.0f;
#pragma unroll 4
    for (int c = 0; c < NCHUNK; c++) {
        int o = (b * NCHUNK + c) * N2;
        g_carry[o + p] = sr;
        g_carry[o + PP + p] = si;
        float cr = g_cs[o + p], ci = g_cs[o + PP + p];
        float nr = fmaf(tr, sr, fmaf(-ti, si, cr));
        float ni = fmaf(tr, si, fmaf(ti, sr, ci));
        sr = nr; si = ni;
    }
}

// apply carry + convert xs to bf16 hi/lo planes (consumed by gemm2)
__global__ void k_apply() {
    const int b = blockIdx.x >> 6;
    const int c = blockIdx.x & 63;
    const int p = threadIdx.x;
    const int co = (b * NCHUNK + c) * N2;
    const float Sr = (c == 0) ? 0.0f : g_carry[co + p];
    const float Si = (c == 0) ? 0.0f : g_carry[co + PP + p];
    size_t base = (size_t)(b * LEN + c * CHUNK) * N2;
#pragma unroll 4
    for (int j = 0; j < CHUNK; j++) {
        float fr = g_pow[(j + 1) * N2 + p];
        float fi = g_pow[(j + 1) * N2 + PP + p];
        size_t o = base + (size_t)j * N2;
        float lv = g_Bu[o + p], iv = g_Bu[o + PP + p];
        float xr = fmaf(fr, Sr, fmaf(-fi, Si, lv));
        float xi = fmaf(fr, Si, fmaf(fi, Sr, iv));
        bf16 hr = __float2bfloat16(xr);
        bf16 hi2 = __float2bfloat16(xi);
        g_Xh[o + p]      = hr;
        g_Xl[o + p]      = __float2bfloat16(xr - __bfloat162float(hr));
        g_Xh[o + PP + p] = hi2;
        g_Xl[o + PP + p] = __float2bfloat16(xi - __bfloat162float(hi2));
    }
}

// ------------------------------ launcher -----------------------------------
extern "C" void kernel_launch(void* const* d_in, const int* in_sizes, int n_in,
                              void* d_out, int out_size) {
    (void)in_sizes; (void)n_in; (void)out_size;
    const float* x     = (const float*)d_in[0];
    const float* lre   = (const float*)d_in[1];
    const float* lim   = (const float*)d_in[2];
    const float* Bm    = (const float*)d_in[3];
    const float* Cm    = (const float*)d_in[4];
    const float* D     = (const float*)d_in[5];
    const float* lstep = (const float*)d_in[6];
    float* out = (float*)d_out;

    cudaFuncSetAttribute(k_gemm1, cudaFuncAttributeMaxDynamicSharedMemorySize, GSMEM);
    cudaFuncSetAttribute(k_gemm2, cudaFuncAttributeMaxDynamicSharedMemorySize, GSMEM);

    k_setup<<<1, 256>>>(lre, lim, lstep);
    k_fill<<<(N2 * HH + 255) / 256, 256>>>(Bm, Cm);
    k_xconv<<<(MT * N2 / 4) / 256, 256>>>(x);

    dim3 gg(NT / 128, MT / 128);  // (4, 256)
    k_gemm1<<<gg, 256, GSMEM>>>();
    k_scan_local<<<BSZ * NCHUNK, 256>>>();
    k_chunkscan<<<BSZ, 256>>>();
    k_apply<<<BSZ * NCHUNK, 256>>>();
    k_gemm2<<<gg, 256, GSMEM>>>(x, D, out);
}

// round 10
// speedup vs baseline: 2.0742x; 2.0742x over previous
#include <cuda_runtime.h>
#include <cuda_bf16.h>
#include <cstdint>

// ---------------------------------------------------------------------------
// SSMDecoder: ys = 2*Re( scan(exp(L*dt), x@B_bar^T) @ C^T ) + D*x
// Bsz=8, L=4096, H=512, P=256 (complex state as re/im planes, N2=512).
// GEMMs: mma.sync m16n8k16 bf16, 3x hi/lo split, cp.async 4-stage pipeline.
// ---------------------------------------------------------------------------

#define BSZ 8
#define LEN 4096
#define HH  512
#define PP  256
#define N2  512
#define MT  (BSZ*LEN)           // 32768
#define CHUNK 64
#define NCHUNK (LEN/CHUNK)      // 64
#define KT  512
#define NT  512

typedef __nv_bfloat16 bf16;

// ------------------------------- scratch -----------------------------------
__device__ float g_Bu[(size_t)MT * N2];                    // 64 MB
__device__ __align__(16) bf16 g_xh[(size_t)MT * N2];       // 32 MB
__device__ __align__(16) bf16 g_xl[(size_t)MT * N2];       // 32 MB
__device__ __align__(16) bf16 g_Xh[(size_t)MT * N2];       // 32 MB (xs hi)
__device__ __align__(16) bf16 g_Xl[(size_t)MT * N2];       // 32 MB (xs lo)
__device__ __align__(16) bf16 g_G1h[N2 * HH];
__device__ __align__(16) bf16 g_G1l[N2 * HH];
__device__ __align__(16) bf16 g_G2h[HH * N2];
__device__ __align__(16) bf16 g_G2l[HH * N2];
__device__ float g_lam[2 * PP];
__device__ float g_f[2 * PP];
__device__ float g_pow[(CHUNK + 1) * N2];
__device__ float g_cs[BSZ * NCHUNK * N2];
__device__ float g_carry[BSZ * NCHUNK * N2];

// ------------------------------ helpers ------------------------------------
__device__ __forceinline__ uint32_t smem_u32(const void* p) {
    uint32_t a;
    asm("{ .reg .u64 t; cvta.to.shared.u64 t, %1; cvt.u32.u64 %0, t; }"
        : "=r"(a) : "l"(p));
    return a;
}
__device__ __forceinline__ void ldsm4(uint32_t* r, uint32_t addr) {
    asm volatile("ldmatrix.sync.aligned.m8n8.x4.shared.b16 {%0,%1,%2,%3}, [%4];"
                 : "=r"(r[0]), "=r"(r[1]), "=r"(r[2]), "=r"(r[3]) : "r"(addr));
}
__device__ __forceinline__ void mma_bf16(float* c, const uint32_t* a, const uint32_t* b) {
    asm volatile(
        "mma.sync.aligned.m16n8k16.row.col.f32.bf16.bf16.f32 "
        "{%0,%1,%2,%3}, {%4,%5,%6,%7}, {%8,%9}, {%0,%1,%2,%3};"
        : "+f"(c[0]), "+f"(c[1]), "+f"(c[2]), "+f"(c[3])
        : "r"(a[0]), "r"(a[1]), "r"(a[2]), "r"(a[3]), "r"(b[0]), "r"(b[1]));
}
__device__ __forceinline__ uint32_t packbf(float x, float y) {
    __nv_bfloat162 t = __floats2bfloat162_rn(x, y);
    return *reinterpret_cast<uint32_t*>(&t);
}
#define CP16(dst, src) \
    asm volatile("cp.async.cg.shared.global [%0], [%1], 16;" :: "r"(dst), "l"(src) : "memory")
#define CP_COMMIT asm volatile("cp.async.commit_group;" ::: "memory")
#define CP_WAIT(n) asm volatile("cp.async.wait_group %0;" :: "n"(n) : "memory")

// ------------------------------- setup -------------------------------------
__global__ void k_setup(const float* __restrict__ lre,
                        const float* __restrict__ lim,
                        const float* __restrict__ lstep) {
    int p = threadIdx.x;
    if (p >= PP) return;
    float st = expf(lstep[p]);
    float ar = lre[p], ai = lim[p];
    float e  = expf(ar * st);
    float th = ai * st;
    float lr = e * cosf(th), li = e * sinf(th);
    g_lam[p] = lr; g_lam[PP + p] = li;
    float nr = lr - 1.0f, ni = li;
    float den = ar * ar + ai * ai;
    g_f[p]      = (nr * ar + ni * ai) / den;
    g_f[PP + p] = (ni * ar - nr * ai) / den;
    float pr = 1.0f, pi = 0.0f;
    for (int k = 0; k <= CHUNK; k++) {
        g_pow[k * N2 + p]      = pr;
        g_pow[k * N2 + PP + p] = pi;
        float t = pr * lr - pi * li;
        pi = pr * li + pi * lr;
        pr = t;
    }
}

__global__ void k_fill(const float* __restrict__ Bm, const float* __restrict__ Cm) {
    int tid = blockIdx.x * blockDim.x + threadIdx.x;
    if (tid >= N2 * HH) return;
    {   // G1[n][h]
        int n = tid / HH, h = tid - n * HH;
        int p = n & (PP - 1);
        float fr = g_f[p], fi = g_f[PP + p];
        float b0 = Bm[(p * HH + h) * 2], b1 = Bm[(p * HH + h) * 2 + 1];
        float v = (n < PP) ? (fr * b0 - fi * b1) : (fr * b1 + fi * b0);
        bf16 hi = __float2bfloat16(v);
        g_G1h[tid] = hi;
        g_G1l[tid] = __float2bfloat16(v - __bfloat162float(hi));
    }
    {   // G2[h][n]
        int h = tid / N2, n = tid - h * N2;
        float v;
        if (n < PP) v =  2.0f * Cm[(h * PP + n) * 2];
        else        v = -2.0f * Cm[(h * PP + (n - PP)) * 2 + 1];
        bf16 hi = __float2bfloat16(v);
        g_G2h[tid] = hi;
        g_G2l[tid] = __float2bfloat16(v - __bfloat162float(hi));
    }
}

// x -> bf16 hi/lo planes (one shot)
__global__ void k_xconv(const float* __restrict__ x) {
    size_t i4 = (size_t)blockIdx.x * blockDim.x + threadIdx.x;
    float4 v = *(const float4*)(x + i4 * 4);
    float h0 = __bfloat162float(__float2bfloat16(v.x));
    float h1 = __bfloat162float(__float2bfloat16(v.y));
    float h2 = __bfloat162float(__float2bfloat16(v.z));
    float h3 = __bfloat162float(__float2bfloat16(v.w));
    uint2 hp = make_uint2(packbf(h0, h1), packbf(h2, h3));
    uint2 lp = make_uint2(packbf(v.x - h0, v.y - h1), packbf(v.z - h2, v.w - h3));
    *(uint2*)(g_xh + i4 * 4) = hp;
    *(uint2*)(g_xl + i4 * 4) = lp;
}

// --------------------------- mma.sync GEMM ---------------------------------
// CTA 128x128, K-chunk 16, 256 threads = 8 warps (2M x 4N), warp 64x32.
// SMEM: 4 stages x 4 bf16 planes (Ah, Al, Bh, Bl), rows padded to 24 bf16.
// cp.async (LDGSTS) pipeline, no register staging.

#define AROW  24
#define PLANE (128 * AROW * 2)          // 6144 B
#define STAGE (4 * PLANE)               // 24576 B
#define NSTG  4
#define GSMEM (NSTG * STAGE)            // 98304 B

template <bool EPI>
__device__ __forceinline__ void gemm_mma(const bf16* __restrict__ Ah,
                                         const bf16* __restrict__ Al,
                                         const bf16* __restrict__ Bh,
                                         const bf16* __restrict__ Bl,
                                         float* __restrict__ Cg,
                                         const float* __restrict__ Xg,
                                         const float* __restrict__ Dg) {
    extern __shared__ __align__(16) char smem[];
    const uint32_t sb = smem_u32(smem);
    const int tid = threadIdx.x;
    const int wid = tid >> 5;
    const int l   = tid & 31;
    const int warp_m = wid >> 2;
    const int warp_n = wid & 3;
    const int rowBase = blockIdx.y * 128;
    const int colBase = blockIdx.x * 128;

    // cp.async mapping: thread covers row rr=tid>>1, chunk c8=tid&1 of all 4 planes
    const int rr = tid >> 1;
    const int c8 = tid & 1;
    const bf16* s0 = Ah + (size_t)(rowBase + rr) * KT + c8 * 8;
    const bf16* s1 = Al + (size_t)(rowBase + rr) * KT + c8 * 8;
    const bf16* s2 = Bh + (size_t)(colBase + rr) * KT + c8 * 8;
    const bf16* s3 = Bl + (size_t)(colBase + rr) * KT + c8 * 8;
    const uint32_t dA = sb + rr * (AROW * 2) + c8 * 16;

#define ISSUE(stg, kt) do { \
    uint32_t so_ = dA + (stg) * STAGE; \
    size_t ko_ = (size_t)(kt) * 16; \
    CP16(so_,             s0 + ko_); \
    CP16(so_ + PLANE,     s1 + ko_); \
    CP16(so_ + 2 * PLANE, s2 + ko_); \
    CP16(so_ + 3 * PLANE, s3 + ko_); \
} while (0)

    float acc[4][4][4];
#pragma unroll
    for (int i = 0; i < 4; i++)
#pragma unroll
        for (int j = 0; j < 4; j++)
#pragma unroll
            for (int k = 0; k < 4; k++) acc[i][j][k] = 0.0f;

    ISSUE(0, 0); CP_COMMIT;
    ISSUE(1, 1); CP_COMMIT;
    ISSUE(2, 2); CP_COMMIT;

    const int a_row = l & 15;
    const int a_k   = (l >> 4) * 8;
    const int b_row = (l & 7) + ((l >> 4) << 3);
    const int b_k   = ((l >> 3) & 1) * 8;
    const uint32_t aoff = (uint32_t)(((warp_m * 64 + a_row) * AROW + a_k) * 2);
    const uint32_t boff = (uint32_t)(((warp_n * 32 + b_row) * AROW + b_k) * 2);

    for (int kt = 0; kt < 32; kt++) {
        CP_WAIT(2);
        __syncthreads();
        if (kt + 3 < 32) ISSUE((kt + 3) & 3, kt + 3);
        CP_COMMIT;

        const uint32_t base = sb + (kt & 3) * STAGE;
        uint32_t bHr[2][4], bLr[2][4];
#pragma unroll
        for (int nb = 0; nb < 2; nb++) {
            uint32_t off = boff + (uint32_t)(nb * 16 * AROW * 2);
            ldsm4(bHr[nb], base + 2 * PLANE + off);
            ldsm4(bLr[nb], base + 3 * PLANE + off);
        }
#pragma unroll
        for (int mt = 0; mt < 4; mt++) {
            uint32_t aHr[4], aLr[4];
            uint32_t off = aoff + (uint32_t)(mt * 16 * AROW * 2);
            ldsm4(aHr, base + off);
            ldsm4(aLr, base + PLANE + off);
#pragma unroll
            for (int nt = 0; nt < 4; nt++)
                mma_bf16(acc[mt][nt], aHr, &bHr[nt >> 1][(nt & 1) * 2]);
#pragma unroll
            for (int nt = 0; nt < 4; nt++)
                mma_bf16(acc[mt][nt], aLr, &bHr[nt >> 1][(nt & 1) * 2]);
#pragma unroll
            for (int nt = 0; nt < 4; nt++)
                mma_bf16(acc[mt][nt], aHr, &bLr[nt >> 1][(nt & 1) * 2]);
        }
    }
#undef ISSUE

    // ---- epilogue ----
    const int r0 = l >> 2;
    const int cp = (l & 3) * 2;
#pragma unroll
    for (int mt = 0; mt < 4; mt++) {
#pragma unroll
        for (int nt = 0; nt < 4; nt++) {
            const int row = rowBase + warp_m * 64 + mt * 16 + r0;
            const int col = colBase + warp_n * 32 + nt * 8 + cp;
            float2 v0 = make_float2(acc[mt][nt][0], acc[mt][nt][1]);
            float2 v1 = make_float2(acc[mt][nt][2], acc[mt][nt][3]);
            size_t o0 = (size_t)row * NT + col;
            size_t o1 = (size_t)(row + 8) * NT + col;
            if (EPI) {
                float2 d  = *(const float2*)(Dg + col);
                float2 x0 = *(const float2*)(Xg + o0);
                float2 x1 = *(const float2*)(Xg + o1);
                v0.x += d.x * x0.x; v0.y += d.y * x0.y;
                v1.x += d.x * x1.x; v1.y += d.y * x1.y;
            }
            *(float2*)(Cg + o0) = v0;
            *(float2*)(Cg + o1) = v1;
        }
    }
}

__global__ __launch_bounds__(256, 2) void k_gemm1() {
    gemm_mma<false>(g_xh, g_xl, g_G1h, g_G1l, g_Bu, nullptr, nullptr);
}
__global__ __launch_bounds__(256, 2) void k_gemm2(const float* __restrict__ x,
                                                  const float* __restrict__ D,
                                                  float* __restrict__ out) {
    gemm_mma<true>(g_Xh, g_Xl, g_G2h, g_G2l, out, x, D);
}

// ------------------------------- scan --------------------------------------
__global__ void k_scan_local() {
    const int b = blockIdx.x >> 6;
    const int c = blockIdx.x & 63;
    const int p = threadIdx.x;
    const float lr = g_lam[p], li = g_lam[PP + p];
    float sr = 0.0f, si = 0.0f;
    size_t base = (size_t)(b * LEN + c * CHUNK) * N2;
#pragma unroll 4
    for (int j = 0; j < CHUNK; j++) {
        size_t o = base + (size_t)j * N2;
        float ur = g_Bu[o + p], ui = g_Bu[o + PP + p];
        float nr = fmaf(lr, sr, fmaf(-li, si, ur));
        float ni = fmaf(lr, si, fmaf(li, sr, ui));
        g_Bu[o + p] = nr;
        g_Bu[o + PP + p] = ni;
        sr = nr; si = ni;
    }
    int co = (b * NCHUNK + c) * N2;
    g_cs[co + p] = sr;
    g_cs[co + PP + p] = si;
}

__global__ void k_chunkscan() {
    const int b = blockIdx.x;
    const int p = threadIdx.x;
    const float tr = g_pow[CHUNK * N2 + p], ti = g_pow[CHUNK * N2 + PP + p];
    float sr = 0.0f, si = 0.0f;
#pragma unroll 4
    for (int c = 0; c < NCHUNK; c++) {
        int o = (b * NCHUNK + c) * N2;
        g_carry[o + p] = sr;
        g_carry[o + PP + p] = si;
        float cr = g_cs[o + p], ci = g_cs[o + PP + p];
        float nr = fmaf(tr, sr, fmaf(-ti, si, cr));
        float ni = fmaf(tr, si, fmaf(ti, sr, ci));
        sr = nr; si = ni;
    }
}

// apply carry + convert xs to bf16 hi/lo planes (consumed by gemm2)
__global__ void k_apply() {
    const int b = blockIdx.x >> 6;
    const int c = blockIdx.x & 63;
    const int p = threadIdx.x;
    const int co = (b * NCHUNK + c) * N2;
    const float Sr = (c == 0) ? 0.0f : g_carry[co + p];
    const float Si = (c == 0) ? 0.0f : g_carry[co + PP + p];
    size_t base = (size_t)(b * LEN + c * CHUNK) * N2;
#pragma unroll 4
    for (int j = 0; j < CHUNK; j++) {
        float fr = g_pow[(j + 1) * N2 + p];
        float fi = g_pow[(j + 1) * N2 + PP + p];
        size_t o = base + (size_t)j * N2;
        float lv = g_Bu[o + p], iv = g_Bu[o + PP + p];
        float xr = fmaf(fr, Sr, fmaf(-fi, Si, lv));
        float xi = fmaf(fr, Si, fmaf(fi, Sr, iv));
        bf16 hr = __float2bfloat16(xr);
        bf16 hi2 = __float2bfloat16(xi);
        g_Xh[o + p]      = hr;
        g_Xl[o + p]      = __float2bfloat16(xr - __bfloat162float(hr));
        g_Xh[o + PP + p] = hi2;
        g_Xl[o + PP + p] = __float2bfloat16(xi - __bfloat162float(hi2));
    }
}

// ------------------------------ launcher -----------------------------------
extern "C" void kernel_launch(void* const* d_in, const int* in_sizes, int n_in,
                              void* d_out, int out_size) {
    (void)in_sizes; (void)n_in; (void)out_size;
    const float* x     = (const float*)d_in[0];
    const float* lre   = (const float*)d_in[1];
    const float* lim   = (const float*)d_in[2];
    const float* Bm    = (const float*)d_in[3];
    const float* Cm    = (const float*)d_in[4];
    const float* D     = (const float*)d_in[5];
    const float* lstep = (const float*)d_in[6];
    float* out = (float*)d_out;

    cudaFuncSetAttribute(k_gemm1, cudaFuncAttributeMaxDynamicSharedMemorySize, GSMEM);
    cudaFuncSetAttribute(k_gemm2, cudaFuncAttributeMaxDynamicSharedMemorySize, GSMEM);

    k_setup<<<1, 256>>>(lre, lim, lstep);
    k_fill<<<(N2 * HH + 255) / 256, 256>>>(Bm, Cm);
    k_xconv<<<(MT * N2 / 4) / 256, 256>>>(x);

    dim3 gg(NT / 128, MT / 128);  // (4, 256)
    k_gemm1<<<gg, 256, GSMEM>>>();
    k_scan_local<<<BSZ * NCHUNK, 256>>>();
    k_chunkscan<<<BSZ, 256>>>();
    k_apply<<<BSZ * NCHUNK, 256>>>();
    k_gemm2<<<gg, 256, GSMEM>>>(x, D, out);
}

// round 11
// speedup vs baseline: 2.9705x; 1.4321x over previous
#include <cuda_runtime.h>
#include <cuda_fp16.h>
#include <cstdint>

// ---------------------------------------------------------------------------
// SSMDecoder: ys = 2*Re( scan(exp(L*dt), x@B_bar^T) @ C^T ) + D*x
// Bsz=8, L=4096, H=512, P=256 (complex state as re/im planes, N2=512).
// GEMMs: mma.sync m16n8k16 fp16, 2-pass (A single fp16, B fp16 hi/lo split),
// cp.async 5-stage pipeline. Scan suite fused to minimize HBM traffic.
// ---------------------------------------------------------------------------

#define BSZ 8
#define LEN 4096
#define HH  512
#define PP  256
#define N2  512
#define MT  (BSZ*LEN)           // 32768
#define CHUNK 64
#define NCHUNK (LEN/CHUNK)      // 64
#define KT  512
#define NT  512

typedef __half fp16;

// ------------------------------- scratch -----------------------------------
__device__ float g_Bu[(size_t)MT * N2];                    // 64 MB
__device__ __align__(16) fp16 g_xf[(size_t)MT * N2];       // 32 MB (x  fp16)
__device__ __align__(16) fp16 g_Xf[(size_t)MT * N2];       // 32 MB (xs fp16)
__device__ __align__(16) fp16 g_G1h[N2 * HH];
__device__ __align__(16) fp16 g_G1l[N2 * HH];
__device__ __align__(16) fp16 g_G2h[HH * N2];
__device__ __align__(16) fp16 g_G2l[HH * N2];
__device__ float g_lam[2 * PP];
__device__ float g_f[2 * PP];
__device__ float g_pow[(CHUNK + 1) * N2];
__device__ float g_cs[BSZ * NCHUNK * N2];
__device__ float g_carry[BSZ * NCHUNK * N2];

// ------------------------------ helpers ------------------------------------
__device__ __forceinline__ uint32_t smem_u32(const void* p) {
    uint32_t a;
    asm("{ .reg .u64 t; cvta.to.shared.u64 t, %1; cvt.u32.u64 %0, t; }"
        : "=r"(a) : "l"(p));
    return a;
}
__device__ __forceinline__ void ldsm4(uint32_t* r, uint32_t addr) {
    asm volatile("ldmatrix.sync.aligned.m8n8.x4.shared.b16 {%0,%1,%2,%3}, [%4];"
                 : "=r"(r[0]), "=r"(r[1]), "=r"(r[2]), "=r"(r[3]) : "r"(addr));
}
__device__ __forceinline__ void mma_f16(float* c, const uint32_t* a, const uint32_t* b) {
    asm volatile(
        "mma.sync.aligned.m16n8k16.row.col.f32.f16.f16.f32 "
        "{%0,%1,%2,%3}, {%4,%5,%6,%7}, {%8,%9}, {%0,%1,%2,%3};"
        : "+f"(c[0]), "+f"(c[1]), "+f"(c[2]), "+f"(c[3])
        : "r"(a[0]), "r"(a[1]), "r"(a[2]), "r"(a[3]), "r"(b[0]), "r"(b[1]));
}
__device__ __forceinline__ uint32_t packh(float x, float y) {
    __half2 t = __floats2half2_rn(x, y);
    return *reinterpret_cast<uint32_t*>(&t);
}
#define CP16(dst, src) \
    asm volatile("cp.async.cg.shared.global [%0], [%1], 16;" :: "r"(dst), "l"(src) : "memory")
#define CP_COMMIT asm volatile("cp.async.commit_group;" ::: "memory")
#define CP_WAIT(n) asm volatile("cp.async.wait_group %0;" :: "n"(n) : "memory")

// ------------------------------- setup -------------------------------------
__global__ void k_setup(const float* __restrict__ lre,
                        const float* __restrict__ lim,
                        const float* __restrict__ lstep) {
    int p = threadIdx.x;
    if (p >= PP) return;
    float st = expf(lstep[p]);
    float ar = lre[p], ai = lim[p];
    float e  = expf(ar * st);
    float th = ai * st;
    float lr = e * cosf(th), li = e * sinf(th);
    g_lam[p] = lr; g_lam[PP + p] = li;
    float nr = lr - 1.0f, ni = li;
    float den = ar * ar + ai * ai;
    g_f[p]      = (nr * ar + ni * ai) / den;
    g_f[PP + p] = (ni * ar - nr * ai) / den;
    float pr = 1.0f, pi = 0.0f;
    for (int k = 0; k <= CHUNK; k++) {
        g_pow[k * N2 + p]      = pr;
        g_pow[k * N2 + PP + p] = pi;
        float t = pr * lr - pi * li;
        pi = pr * li + pi * lr;
        pr = t;
    }
}

__global__ void k_fill(const float* __restrict__ Bm, const float* __restrict__ Cm) {
    int tid = blockIdx.x * blockDim.x + threadIdx.x;
    if (tid >= N2 * HH) return;
    {   // G1[n][h]
        int n = tid / HH, h = tid - n * HH;
        int p = n & (PP - 1);
        float fr = g_f[p], fi = g_f[PP + p];
        float b0 = Bm[(p * HH + h) * 2], b1 = Bm[(p * HH + h) * 2 + 1];
        float v = (n < PP) ? (fr * b0 - fi * b1) : (fr * b1 + fi * b0);
        fp16 hi = __float2half_rn(v);
        g_G1h[tid] = hi;
        g_G1l[tid] = __float2half_rn(v - __half2float(hi));
    }
    {   // G2[h][n]
        int h = tid / N2, n = tid - h * N2;
        float v;
        if (n < PP) v =  2.0f * Cm[(h * PP + n) * 2];
        else        v = -2.0f * Cm[(h * PP + (n - PP)) * 2 + 1];
        fp16 hi = __float2half_rn(v);
        g_G2h[tid] = hi;
        g_G2l[tid] = __float2half_rn(v - __half2float(hi));
    }
}

// x -> fp16 plane (one shot)
__global__ void k_xconv(const float* __restrict__ x) {
    size_t i4 = (size_t)blockIdx.x * blockDim.x + threadIdx.x;
    float4 v = *(const float4*)(x + i4 * 4);
    uint2 hp = make_uint2(packh(v.x, v.y), packh(v.z, v.w));
    *(uint2*)(g_xf + i4 * 4) = hp;
}

// --------------------------- mma.sync GEMM ---------------------------------
// CTA 128x128, K-chunk 16, 256 threads = 8 warps (2M x 4N), warp 64x32.
// SMEM: 5 stages x 3 fp16 planes (A, Bh, Bl), rows padded to 24 halves.
// 2-pass: D = A*Bh + A*Bl.

#define AROW  24
#define PLANE (128 * AROW * 2)          // 6144 B
#define STAGE (3 * PLANE)               // 18432 B
#define NSTG  5
#define GSMEM (NSTG * STAGE)            // 92160 B

template <bool EPI>
__device__ __forceinline__ void gemm_mma(const fp16* __restrict__ Af,
                                         const fp16* __restrict__ Bh,
                                         const fp16* __restrict__ Bl,
                                         float* __restrict__ Cg,
                                         const float* __restrict__ Xg,
                                         const float* __restrict__ Dg) {
    extern __shared__ __align__(16) char smem[];
    const uint32_t sb = smem_u32(smem);
    const int tid = threadIdx.x;
    const int wid = tid >> 5;
    const int l   = tid & 31;
    const int warp_m = wid >> 2;
    const int warp_n = wid & 3;
    const int rowBase = blockIdx.y * 128;
    const int colBase = blockIdx.x * 128;

    // cp.async mapping: thread -> row rr=tid>>1, 16B chunk c8=tid&1, x3 planes
    const int rr = tid >> 1;
    const int c8 = tid & 1;
    const fp16* s0 = Af + (size_t)(rowBase + rr) * KT + c8 * 8;
    const fp16* s1 = Bh + (size_t)(colBase + rr) * KT + c8 * 8;
    const fp16* s2 = Bl + (size_t)(colBase + rr) * KT + c8 * 8;
    const uint32_t dA = sb + rr * (AROW * 2) + c8 * 16;

#define ISSUE(stg, kt) do { \
    uint32_t so_ = dA + (stg) * STAGE; \
    size_t ko_ = (size_t)(kt) * 16; \
    CP16(so_,             s0 + ko_); \
    CP16(so_ + PLANE,     s1 + ko_); \
    CP16(so_ + 2 * PLANE, s2 + ko_); \
} while (0)

    float acc[4][4][4];
#pragma unroll
    for (int i = 0; i < 4; i++)
#pragma unroll
        for (int j = 0; j < 4; j++)
#pragma unroll
            for (int k = 0; k < 4; k++) acc[i][j][k] = 0.0f;

    ISSUE(0, 0); CP_COMMIT;
    ISSUE(1, 1); CP_COMMIT;
    ISSUE(2, 2); CP_COMMIT;
    ISSUE(3, 3); CP_COMMIT;

    const int a_row = l & 15;
    const int a_k   = (l >> 4) * 8;
    const int b_row = (l & 7) + ((l >> 4) << 3);
    const int b_k   = ((l >> 3) & 1) * 8;
    const uint32_t aoff = (uint32_t)(((warp_m * 64 + a_row) * AROW + a_k) * 2);
    const uint32_t boff = (uint32_t)(((warp_n * 32 + b_row) * AROW + b_k) * 2);

    int stg = 0, pstg = 4;
    for (int kt = 0; kt < 32; kt++) {
        CP_WAIT(3);
        __syncthreads();
        if (kt + 4 < 32) ISSUE(pstg, kt + 4);
        CP_COMMIT;
        if (++pstg == NSTG) pstg = 0;

        const uint32_t base = sb + stg * STAGE;
        if (++stg == NSTG) stg = 0;

        uint32_t bHr[2][4], bLr[2][4];
#pragma unroll
        for (int nb = 0; nb < 2; nb++) {
            uint32_t off = boff + (uint32_t)(nb * 16 * AROW * 2);
            ldsm4(bHr[nb], base + PLANE + off);
            ldsm4(bLr[nb], base + 2 * PLANE + off);
        }
#pragma unroll
        for (int mt = 0; mt < 4; mt++) {
            uint32_t aR[4];
            uint32_t off = aoff + (uint32_t)(mt * 16 * AROW * 2);
            ldsm4(aR, base + off);
#pragma unroll
            for (int nt = 0; nt < 4; nt++)
                mma_f16(acc[mt][nt], aR, &bHr[nt >> 1][(nt & 1) * 2]);
#pragma unroll
            for (int nt = 0; nt < 4; nt++)
                mma_f16(acc[mt][nt], aR, &bLr[nt >> 1][(nt & 1) * 2]);
        }
    }
#undef ISSUE

    // ---- epilogue ----
    const int r0 = l >> 2;
    const int cp = (l & 3) * 2;
#pragma unroll
    for (int mt = 0; mt < 4; mt++) {
#pragma unroll
        for (int nt = 0; nt < 4; nt++) {
            const int row = rowBase + warp_m * 64 + mt * 16 + r0;
            const int col = colBase + warp_n * 32 + nt * 8 + cp;
            float2 v0 = make_float2(acc[mt][nt][0], acc[mt][nt][1]);
            float2 v1 = make_float2(acc[mt][nt][2], acc[mt][nt][3]);
            size_t o0 = (size_t)row * NT + col;
            size_t o1 = (size_t)(row + 8) * NT + col;
            if (EPI) {
                float2 d  = *(const float2*)(Dg + col);
                float2 x0 = *(const float2*)(Xg + o0);
                float2 x1 = *(const float2*)(Xg + o1);
                v0.x += d.x * x0.x; v0.y += d.y * x0.y;
                v1.x += d.x * x1.x; v1.y += d.y * x1.y;
            }
            *(float2*)(Cg + o0) = v0;
            *(float2*)(Cg + o1) = v1;
        }
    }
}

__global__ __launch_bounds__(256, 2) void k_gemm1() {
    gemm_mma<false>(g_xf, g_G1h, g_G1l, g_Bu, nullptr, nullptr);
}
__global__ __launch_bounds__(256, 2) void k_gemm2(const float* __restrict__ x,
                                                  const float* __restrict__ D,
                                                  float* __restrict__ out) {
    gemm_mma<true>(g_Xf, g_G2h, g_G2l, out, x, D);
}

// ------------------------------- scan --------------------------------------
// Pass 1: chunk sums only (read Bu once, write tiny cs).
__global__ void k_sums() {
    const int b = blockIdx.x >> 6;
    const int c = blockIdx.x & 63;
    const int p = threadIdx.x;
    const float lr = g_lam[p], li = g_lam[PP + p];
    float sr = 0.0f, si = 0.0f;
    size_t base = (size_t)(b * LEN + c * CHUNK) * N2;
#pragma unroll 4
    for (int j = 0; j < CHUNK; j++) {
        size_t o = base + (size_t)j * N2;
        float ur = g_Bu[o + p], ui = g_Bu[o + PP + p];
        float nr = fmaf(lr, sr, fmaf(-li, si, ur));
        float ni = fmaf(lr, si, fmaf(li, sr, ui));
        sr = nr; si = ni;
    }
    int co = (b * NCHUNK + c) * N2;
    g_cs[co + p] = sr;
    g_cs[co + PP + p] = si;
}

// Pass 2: scan of chunk sums with multiplier lam^64 -> carries.
__global__ void k_chunkscan() {
    const int b = blockIdx.x;
    const int p = threadIdx.x;
    const float tr = g_pow[CHUNK * N2 + p], ti = g_pow[CHUNK * N2 + PP + p];
    float sr = 0.0f, si = 0.0f;
#pragma unroll 4
    for (int c = 0; c < NCHUNK; c++) {
        int o = (b * NCHUNK + c) * N2;
        g_carry[o + p] = sr;
        g_carry[o + PP + p] = si;
        float cr = g_cs[o + p], ci = g_cs[o + PP + p];
        float nr = fmaf(tr, sr, fmaf(-ti, si, cr));
        float ni = fmaf(tr, si, fmaf(ti, sr, ci));
        sr = nr; si = ni;
    }
}

// Pass 3: local scan seeded with carry, write xs directly as fp16.
__global__ void k_scanapply() {
    const int b = blockIdx.x >> 6;
    const int c = blockIdx.x & 63;
    const int p = threadIdx.x;
    const float lr = g_lam[p], li = g_lam[PP + p];
    const int co = (b * NCHUNK + c) * N2;
    float sr = (c == 0) ? 0.0f : g_carry[co + p];
    float si = (c == 0) ? 0.0f : g_carry[co + PP + p];
    size_t base = (size_t)(b * LEN + c * CHUNK) * N2;
#pragma unroll 4
    for (int j = 0; j < CHUNK; j++) {
        size_t o = base + (size_t)j * N2;
        float ur = g_Bu[o + p], ui = g_Bu[o + PP + p];
        float nr = fmaf(lr, sr, fmaf(-li, si, ur));
        float ni = fmaf(lr, si, fmaf(li, sr, ui));
        g_Xf[o + p]      = __float2half_rn(nr);
        g_Xf[o + PP + p] = __float2half_rn(ni);
        sr = nr; si = ni;
    }
}

// ------------------------------ launcher -----------------------------------
extern "C" void kernel_launch(void* const* d_in, const int* in_sizes, int n_in,
                              void* d_out, int out_size) {
    (void)in_sizes; (void)n_in; (void)out_size;
    const float* x     = (const float*)d_in[0];
    const float* lre   = (const float*)d_in[1];
    const float* lim   = (const float*)d_in[2];
    const float* Bm    = (const float*)d_in[3];
    const float* Cm    = (const float*)d_in[4];
    const float* D     = (const float*)d_in[5];
    const float* lstep = (const float*)d_in[6];
    float* out = (float*)d_out;

    cudaFuncSetAttribute(k_gemm1, cudaFuncAttributeMaxDynamicSharedMemorySize, GSMEM);
    cudaFuncSetAttribute(k_gemm2, cudaFuncAttributeMaxDynamicSharedMemorySize, GSMEM);

    k_setup<<<1, 256>>>(lre, lim, lstep);
    k_fill<<<(N2 * HH + 255) / 256, 256>>>(Bm, Cm);
    k_xconv<<<(MT * N2 / 4) / 256, 256>>>(x);

    dim3 gg(NT / 128, MT / 128);  // (4, 256)
    k_gemm1<<<gg, 256, GSMEM>>>();
    k_sums<<<BSZ * NCHUNK, 256>>>();
    k_chunkscan<<<BSZ, 256>>>();
    k_scanapply<<<BSZ * NCHUNK, 256>>>();
    k_gemm2<<<gg, 256, GSMEM>>>(x, D, out);
}

// round 13
// speedup vs baseline: 4.5063x; 1.5170x over previous
#include <cuda_runtime.h>
#include <cuda_fp16.h>
#include <cstdint>

// ---------------------------------------------------------------------------
// SSMDecoder: ys = 2*Re( scan(exp(L*dt), x@B_bar^T) @ C^T ) + D*x
// Bsz=8, L=4096, H=512, P=256 (complex state as re/im planes, N2=512).
// GEMMs: mma.sync m16n8k16 fp16 single-pass, cp.async 6-stage pipeline.
// Bu stored fp16 (halves gemm1 store + scan read traffic).
// ---------------------------------------------------------------------------

#define BSZ 8
#define LEN 4096
#define HH  512
#define PP  256
#define N2  512
#define MT  (BSZ*LEN)           // 32768
#define CHUNK 64
#define NCHUNK (LEN/CHUNK)      // 64
#define KT  512
#define NT  512

typedef __half fp16;

// ------------------------------- scratch -----------------------------------
__device__ __align__(16) fp16 g_Buh[(size_t)MT * N2];      // 32 MB (Bu fp16)
__device__ __align__(16) fp16 g_xf[(size_t)MT * N2];       // 32 MB (x  fp16)
__device__ __align__(16) fp16 g_Xf[(size_t)MT * N2];       // 32 MB (xs fp16)
__device__ __align__(16) fp16 g_G1f[N2 * HH];
__device__ __align__(16) fp16 g_G2f[HH * N2];
__device__ float g_lam[2 * PP];
__device__ float g_f[2 * PP];
__device__ float g_pow[(CHUNK + 1) * N2];
__device__ float g_cs[BSZ * NCHUNK * N2];
__device__ float g_carry[BSZ * NCHUNK * N2];

// ------------------------------ helpers ------------------------------------
__device__ __forceinline__ uint32_t smem_u32(const void* p) {
    uint32_t a;
    asm("{ .reg .u64 t; cvta.to.shared.u64 t, %1; cvt.u32.u64 %0, t; }"
        : "=r"(a) : "l"(p));
    return a;
}
__device__ __forceinline__ void ldsm4(uint32_t* r, uint32_t addr) {
    asm volatile("ldmatrix.sync.aligned.m8n8.x4.shared.b16 {%0,%1,%2,%3}, [%4];"
                 : "=r"(r[0]), "=r"(r[1]), "=r"(r[2]), "=r"(r[3]) : "r"(addr));
}
__device__ __forceinline__ void mma_f16(float* c, const uint32_t* a, const uint32_t* b) {
    asm volatile(
        "mma.sync.aligned.m16n8k16.row.col.f32.f16.f16.f32 "
        "{%0,%1,%2,%3}, {%4,%5,%6,%7}, {%8,%9}, {%0,%1,%2,%3};"
        : "+f"(c[0]), "+f"(c[1]), "+f"(c[2]), "+f"(c[3])
        : "r"(a[0]), "r"(a[1]), "r"(a[2]), "r"(a[3]), "r"(b[0]), "r"(b[1]));
}
__device__ __forceinline__ uint32_t packh(float x, float y) {
    __half2 t = __floats2half2_rn(x, y);
    return *reinterpret_cast<uint32_t*>(&t);
}
#define CP16(dst, src) \
    asm volatile("cp.async.cg.shared.global [%0], [%1], 16;" :: "r"(dst), "l"(src) : "memory")
#define CP_COMMIT asm volatile("cp.async.commit_group;" ::: "memory")
#define CP_WAIT(n) asm volatile("cp.async.wait_group %0;" :: "n"(n) : "memory")

// ------------------------------- setup -------------------------------------
__global__ void k_setup(const float* __restrict__ lre,
                        const float* __restrict__ lim,
                        const float* __restrict__ lstep) {
    int p = threadIdx.x;
    if (p >= PP) return;
    float st = expf(lstep[p]);
    float ar = lre[p], ai = lim[p];
    float e  = expf(ar * st);
    float th = ai * st;
    float lr = e * cosf(th), li = e * sinf(th);
    g_lam[p] = lr; g_lam[PP + p] = li;
    float nr = lr - 1.0f, ni = li;
    float den = ar * ar + ai * ai;
    g_f[p]      = (nr * ar + ni * ai) / den;
    g_f[PP + p] = (ni * ar - nr * ai) / den;
    float pr = 1.0f, pi = 0.0f;
    for (int k = 0; k <= CHUNK; k++) {
        g_pow[k * N2 + p]      = pr;
        g_pow[k * N2 + PP + p] = pi;
        float t = pr * lr - pi * li;
        pi = pr * li + pi * lr;
        pr = t;
    }
}

__global__ void k_fill(const float* __restrict__ Bm, const float* __restrict__ Cm) {
    int tid = blockIdx.x * blockDim.x + threadIdx.x;
    if (tid >= N2 * HH) return;
    {   // G1[n][h]
        int n = tid / HH, h = tid - n * HH;
        int p = n & (PP - 1);
        float fr = g_f[p], fi = g_f[PP + p];
        float b0 = Bm[(p * HH + h) * 2], b1 = Bm[(p * HH + h) * 2 + 1];
        float v = (n < PP) ? (fr * b0 - fi * b1) : (fr * b1 + fi * b0);
        g_G1f[tid] = __float2half_rn(v);
    }
    {   // G2[h][n]
        int h = tid / N2, n = tid - h * N2;
        float v;
        if (n < PP) v =  2.0f * Cm[(h * PP + n) * 2];
        else        v = -2.0f * Cm[(h * PP + (n - PP)) * 2 + 1];
        g_G2f[tid] = __float2half_rn(v);
    }
}

// x -> fp16 plane (one shot)
__global__ void k_xconv(const float* __restrict__ x) {
    size_t i4 = (size_t)blockIdx.x * blockDim.x + threadIdx.x;
    float4 v = *(const float4*)(x + i4 * 4);
    uint2 hp = make_uint2(packh(v.x, v.y), packh(v.z, v.w));
    *(uint2*)(g_xf + i4 * 4) = hp;
}

// --------------------------- mma.sync GEMM ---------------------------------
// CTA 128x128, K-chunk 16, 256 threads = 8 warps (2M x 4N), warp 64x32.
// SMEM: 6 stages x 2 fp16 planes (A, B), rows padded to 24 halves.
// Single pass: D = A*B.

#define AROW  24
#define PLANE (128 * AROW * 2)          // 6144 B
#define STAGE (2 * PLANE)               // 12288 B
#define NSTG  6
#define GSMEM (NSTG * STAGE)            // 73728 B

template <bool EPI, bool HOUT>
__device__ __forceinline__ void gemm_mma(const fp16* __restrict__ Af,
                                         const fp16* __restrict__ Bf,
                                         void* __restrict__ Cg,
                                         const float* __restrict__ Xg,
                                         const float* __restrict__ Dg) {
    extern __shared__ __align__(16) char smem[];
    const uint32_t sb = smem_u32(smem);
    const int tid = threadIdx.x;
    const int wid = tid >> 5;
    const int l   = tid & 31;
    const int warp_m = wid >> 2;
    const int warp_n = wid & 3;
    const int rowBase = blockIdx.y * 128;
    const int colBase = blockIdx.x * 128;

    const int rr = tid >> 1;
    const int c8 = tid & 1;
    const fp16* s0 = Af + (size_t)(rowBase + rr) * KT + c8 * 8;
    const fp16* s1 = Bf + (size_t)(colBase + rr) * KT + c8 * 8;
    const uint32_t dA = sb + rr * (AROW * 2) + c8 * 16;

#define ISSUE(stg, kt) do { \
    uint32_t so_ = dA + (stg) * STAGE; \
    size_t ko_ = (size_t)(kt) * 16; \
    CP16(so_,         s0 + ko_); \
    CP16(so_ + PLANE, s1 + ko_); \
} while (0)

    float acc[4][4][4];
#pragma unroll
    for (int i = 0; i < 4; i++)
#pragma unroll
        for (int j = 0; j < 4; j++)
#pragma unroll
            for (int k = 0; k < 4; k++) acc[i][j][k] = 0.0f;

    ISSUE(0, 0); CP_COMMIT;
    ISSUE(1, 1); CP_COMMIT;
    ISSUE(2, 2); CP_COMMIT;
    ISSUE(3, 3); CP_COMMIT;
    ISSUE(4, 4); CP_COMMIT;

    const int a_row = l & 15;
    const int a_k   = (l >> 4) * 8;
    const int b_row = (l & 7) + ((l >> 4) << 3);
    const int b_k   = ((l >> 3) & 1) * 8;
    const uint32_t aoff = (uint32_t)(((warp_m * 64 + a_row) * AROW + a_k) * 2);
    const uint32_t boff = (uint32_t)(((warp_n * 32 + b_row) * AROW + b_k) * 2);

    int stg = 0, pstg = 5;
    for (int kt = 0; kt < 32; kt++) {
        CP_WAIT(4);
        __syncthreads();
        if (kt + 5 < 32) ISSUE(pstg, kt + 5);
        CP_COMMIT;
        if (++pstg == NSTG) pstg = 0;

        const uint32_t base = sb + stg * STAGE;
        if (++stg == NSTG) stg = 0;

        uint32_t bR[2][4];
#pragma unroll
        for (int nb = 0; nb < 2; nb++) {
            uint32_t off = boff + (uint32_t)(nb * 16 * AROW * 2);
            ldsm4(bR[nb], base + PLANE + off);
        }
#pragma unroll
        for (int mt = 0; mt < 4; mt++) {
            uint32_t aR[4];
            uint32_t off = aoff + (uint32_t)(mt * 16 * AROW * 2);
            ldsm4(aR, base + off);
#pragma unroll
            for (int nt = 0; nt < 4; nt++)
                mma_f16(acc[mt][nt], aR, &bR[nt >> 1][(nt & 1) * 2]);
        }
    }
#undef ISSUE

    // ---- epilogue ----
    const int r0 = l >> 2;
    const int cp = (l & 3) * 2;
#pragma unroll
    for (int mt = 0; mt < 4; mt++) {
#pragma unroll
        for (int nt = 0; nt < 4; nt++) {
            const int row = rowBase + warp_m * 64 + mt * 16 + r0;
            const int col = colBase + warp_n * 32 + nt * 8 + cp;
            float2 v0 = make_float2(acc[mt][nt][0], acc[mt][nt][1]);
            float2 v1 = make_float2(acc[mt][nt][2], acc[mt][nt][3]);
            size_t o0 = (size_t)row * NT + col;
            size_t o1 = (size_t)(row + 8) * NT + col;
            if (HOUT) {
                fp16* C = (fp16*)Cg;
                *(uint32_t*)(C + o0) = packh(v0.x, v0.y);
                *(uint32_t*)(C + o1) = packh(v1.x, v1.y);
            } else {
                float* C = (float*)Cg;
                if (EPI) {
                    float2 d  = *(const float2*)(Dg + col);
                    float2 x0 = *(const float2*)(Xg + o0);
                    float2 x1 = *(const float2*)(Xg + o1);
                    v0.x += d.x * x0.x; v0.y += d.y * x0.y;
                    v1.x += d.x * x1.x; v1.y += d.y * x1.y;
                }
                *(float2*)(C + o0) = v0;
                *(float2*)(C + o1) = v1;
            }
        }
    }
}

__global__ __launch_bounds__(256, 2) void k_gemm1() {
    gemm_mma<false, true>(g_xf, g_G1f, g_Buh, nullptr, nullptr);
}
__global__ __launch_bounds__(256, 2) void k_gemm2(const float* __restrict__ x,
                                                  const float* __restrict__ D,
                                                  float* __restrict__ out) {
    gemm_mma<true, false>(g_Xf, g_G2f, out, x, D);
}

// ------------------------------- scan --------------------------------------
// Pass 1: chunk sums only (read Bu fp16 once, write tiny cs).
__global__ void k_sums() {
    const int b = blockIdx.x >> 6;
    const int c = blockIdx.x & 63;
    const int p = threadIdx.x;
    const float lr = g_lam[p], li = g_lam[PP + p];
    float sr = 0.0f, si = 0.0f;
    size_t base = (size_t)(b * LEN + c * CHUNK) * N2;
#pragma unroll 4
    for (int j = 0; j < CHUNK; j++) {
        size_t o = base + (size_t)j * N2;
        float ur = __half2float(g_Buh[o + p]);
        float ui = __half2float(g_Buh[o + PP + p]);
        float nr = fmaf(lr, sr, fmaf(-li, si, ur));
        float ni = fmaf(lr, si, fmaf(li, sr, ui));
        sr = nr; si = ni;
    }
    int co = (b * NCHUNK + c) * N2;
    g_cs[co + p] = sr;
    g_cs[co + PP + p] = si;
}

// Pass 2: scan of chunk sums with multiplier lam^64 -> carries.
__global__ void k_chunkscan() {
    const int b = blockIdx.x;
    const int p = threadIdx.x;
    const float tr = g_pow[CHUNK * N2 + p], ti = g_pow[CHUNK * N2 + PP + p];
    float sr = 0.0f, si = 0.0f;
#pragma unroll 4
    for (int c = 0; c < NCHUNK; c++) {
        int o = (b * NCHUNK + c) * N2;
        g_carry[o + p] = sr;
        g_carry[o + PP + p] = si;
        float cr = g_cs[o + p], ci = g_cs[o + PP + p];
        float nr = fmaf(tr, sr, fmaf(-ti, si, cr));
        float ni = fmaf(tr, si, fmaf(ti, sr, ci));
        sr = nr; si = ni;
    }
}

// Pass 3: local scan seeded with carry, write xs directly as fp16.
__global__ void k_scanapply() {
    const int b = blockIdx.x >> 6;
    const int c = blockIdx.x & 63;
    const int p = threadIdx.x;
    const float lr = g_lam[p], li = g_lam[PP + p];
    const int co = (b * NCHUNK + c) * N2;
    float sr = (c == 0) ? 0.0f : g_carry[co + p];
    float si = (c == 0) ? 0.0f : g_carry[co + PP + p];
    size_t base = (size_t)(b * LEN + c * CHUNK) * N2;
#pragma unroll 4
    for (int j = 0; j < CHUNK; j++) {
        size_t o = base + (size_t)j * N2;
        float ur = __half2float(g_Buh[o + p]);
        float ui = __half2float(g_Buh[o + PP + p]);
        float nr = fmaf(lr, sr, fmaf(-li, si, ur));
        float ni = fmaf(lr, si, fmaf(li, sr, ui));
        g_Xf[o + p]      = __float2half_rn(nr);
        g_Xf[o + PP + p] = __float2half_rn(ni);
        sr = nr; si = ni;
    }
}

// ------------------------------ launcher -----------------------------------
extern "C" void kernel_launch(void* const* d_in, const int* in_sizes, int n_in,
                              void* d_out, int out_size) {
    (void)in_sizes; (void)n_in; (void)out_size;
    const float* x     = (const float*)d_in[0];
    const float* lre   = (const float*)d_in[1];
    const float* lim   = (const float*)d_in[2];
    const float* Bm    = (const float*)d_in[3];
    const float* Cm    = (const float*)d_in[4];
    const float* D     = (const float*)d_in[5];
    const float* lstep = (const float*)d_in[6];
    float* out = (float*)d_out;

    cudaFuncSetAttribute(k_gemm1, cudaFuncAttributeMaxDynamicSharedMemorySize, GSMEM);
    cudaFuncSetAttribute(k_gemm2, cudaFuncAttributeMaxDynamicSharedMemorySize, GSMEM);

    k_setup<<<1, 256>>>(lre, lim, lstep);
    k_fill<<<(N2 * HH + 255) / 256, 256>>>(Bm, Cm);
    k_xconv<<<(MT * N2 / 4) / 256, 256>>>(x);

    dim3 gg(NT / 128, MT / 128);  // (4, 256)
    k_gemm1<<<gg, 256, GSMEM>>>();
    k_sums<<<BSZ * NCHUNK, 256>>>();
    k_chunkscan<<<BSZ, 256>>>();
    k_scanapply<<<BSZ * NCHUNK, 256>>>();
    k_gemm2<<<gg, 256, GSMEM>>>(x, D, out);
}